// round 14
// baseline (speedup 1.0000x reference)
#include <cuda_runtime.h>
#include <cuda_fp16.h>
#include <math.h>
#include <cstdint>

#define B_   32
#define T_   2000
#define H_   256
#define S_   63
#define TRS  64              // g_trans row stride (padded)
#define TM1  1999            // T-1
#define M1   63968           // B*(T-1)
#define M1P  64000           // padded row count
#define K1   512             // 2*H
#define N1   256             // H

// Scratch (device globals: allocation-guard safe)
__device__ __align__(16) float    g_trans[M1P * TRS];     // boundary trans rows only
__device__ __align__(16) uint4    g_w1pack[16384];        // W1^T fp16 A-frags
__device__ __align__(16) uint2    g_w2pack[4096];         // W2 fp16 B-frags

__device__ __forceinline__ uint32_t h2u(__half2 h) {
    return *reinterpret_cast<uint32_t*>(&h);
}

__device__ __forceinline__ void mma_f16(float* c, uint32_t a0, uint32_t a1,
                                        uint32_t a2, uint32_t a3,
                                        uint32_t b0, uint32_t b1) {
    asm volatile(
        "mma.sync.aligned.m16n8k16.row.col.f32.f16.f16.f32 "
        "{%0,%1,%2,%3}, {%4,%5,%6,%7}, {%8,%9}, {%0,%1,%2,%3};"
        : "+f"(c[0]), "+f"(c[1]), "+f"(c[2]), "+f"(c[3])
        : "r"(a0), "r"(a1), "r"(a2), "r"(a3), "r"(b0), "r"(b1));
}

__device__ __forceinline__ void ldsm4(uint32_t& r0, uint32_t& r1,
                                      uint32_t& r2, uint32_t& r3, uint32_t addr) {
    asm volatile("ldmatrix.sync.aligned.m8n8.x4.shared.b16 {%0,%1,%2,%3}, [%4];"
                 : "=r"(r0), "=r"(r1), "=r"(r2), "=r"(r3) : "r"(addr));
}

__device__ __forceinline__ uint32_t smem_u32(const void* p) {
    uint32_t a;
    asm("{ .reg .u64 t; cvta.to.shared.u64 t, %1; cvt.u32.u64 %0, t; }"
        : "=r"(a) : "l"(p));
    return a;
}

__device__ __forceinline__ void softmax_emit(float v0, float v1, bool has1,
                                             float* ob, int lane) {
    float mx = fmaxf(v0, v1);
    #pragma unroll
    for (int o = 16; o > 0; o >>= 1) mx = fmaxf(mx, __shfl_xor_sync(0xffffffff, mx, o));
    float e0 = __expf(v0 - mx);
    float e1 = has1 ? __expf(v1 - mx) : 0.f;
    float sum = e0 + e1;
    #pragma unroll
    for (int o = 16; o > 0; o >>= 1) sum += __shfl_xor_sync(0xffffffff, sum, o);
    float inv = 1.f / sum;
    ob[lane] = e0 * inv;
    if (has1) ob[lane + 32] = e1 * inv;
}

// ===========================================================================
// Prep: coalesced W1 pack (blocks 0..255) + W2 pack (blocks 256..271).
// ===========================================================================
__global__ __launch_bounds__(256) void prep_weights(
    const float* __restrict__ W1, const float* __restrict__ W2)
{
    if (blockIdx.x < 256) {
        int idx = blockIdx.x * 256 + threadIdx.x;   // 0..65535
        int n  = idx & 255;
        int kp = idx >> 8;                          // 0..255, k0 = 2*kp
        __half2 v = __floats2half2_rn(W1[(long)(kp * 2) * N1 + n],
                                      W1[(long)(kp * 2 + 1) * N1 + n]);
        int kstep = kp >> 3;
        int rem   = kp & 7;
        int sub   = rem >> 2;
        int tq    = rem & 3;
        int q   = n >> 5;
        int nr  = n & 31;
        int s   = nr >> 4;
        int w16 = nr & 15;
        int g8  = w16 >> 3;
        int gg  = w16 & 7;
        int lane = gg * 4 + tq;
        long fid = ((long)(q * 32 + kstep) * 2 + s) * 32 + lane;
        reinterpret_cast<uint32_t*>(g_w1pack)[fid * 4 + sub * 2 + g8] = h2u(v);
    } else {
        int idx  = (blockIdx.x - 256) * 256 + threadIdx.x;
        if (idx >= 4096) return;
        int lane = idx & 31;
        int nb   = (idx >> 5) & 7;
        int kt   = idx >> 8;
        int k = kt * 16 + (lane & 3) * 2;
        int n = nb * 8 + (lane >> 2);
        float w00 = (n < S_) ? W2[(long)k * S_ + n]       : 0.f;
        float w01 = (n < S_) ? W2[(long)(k + 1) * S_ + n] : 0.f;
        float w10 = (n < S_) ? W2[(long)(k + 8) * S_ + n] : 0.f;
        float w11 = (n < S_) ? W2[(long)(k + 9) * S_ + n] : 0.f;
        uint2 o;
        o.x = h2u(__floats2half2_rn(w00, w01));
        o.y = h2u(__floats2half2_rn(w10, w11));
        g_w2pack[idx] = o;
    }
}

// ===========================================================================
// Fully fused GEMM1+GEMM2+ALIGN, M=32 tiles (grid 2000):
//   stage full-K pairs tile; zero-sync mainloop (h = relu(pairs@W1+b1));
//   epilogue: trans = h@W2+b2 -> smem tile; per-warp softmax for 4 rows each;
//   boundary rows 0/31 -> g_trans for the cleanup kernel.
// ===========================================================================
#define BROWF 1040   // full-K B row stride bytes (1024 data + 16 pad; ≡16 mod 128)
#define STROFF 20480 // smem offset of trans tile [32][65] floats (8320 B)
__global__ __launch_bounds__(256, 2) void gemm_fused(
    const float* __restrict__ emb, const float* __restrict__ b1,
    const float* __restrict__ b2, const float* __restrict__ logits,
    const int* __restrict__ kw, float* __restrict__ out)
{
    extern __shared__ __align__(16) char dynsm[];
    __half* sT  = reinterpret_cast<__half*>(dynsm);            // [32][264] h tile (alias)
    float*  sTr = reinterpret_cast<float*>(dynsm + STROFF);    // [32][65] trans tile
    const uint32_t sbAddr = smem_u32(dynsm);

    const int tid  = threadIdx.x;
    const int warp = tid >> 5;     // hidden 32-block (0..7)
    const int lane = tid & 31;
    const int g    = lane >> 2;
    const int t    = lane & 3;

    const int lmJ     = (lane >> 4);
    const int lmPiece = (lane >> 3) & 1;
    const int lmRow   = lane & 7;

    // staging mapping: row r = tid>>3; 8 chunks of 8 k at kg = (tid&7)*8 + u*64
    const int r  = tid >> 3;             // 0..31
    const int c8 = (tid & 7) * 8;        // 0..56
    const int mBase = blockIdx.x * 32;
    int m = mBase + r;
    if (m >= M1) m = M1 - 1;
    const int b = m / TM1;
    const int tt = m - b * TM1;
    const float* rowT  = emb + ((long)b * T_ + tt) * H_;   // pairs k>=256
    const float* rowT1 = rowT + H_;                        // pairs k<256

    // ---- stage full K=512 (one pass, conflict-free stores) ----
    {
        #pragma unroll
        for (int u = 0; u < 8; u++) {
            const int kg = c8 + u * 64;
            const float* src = (kg < H_) ? (rowT1 + kg) : (rowT + (kg - H_));
            float4 v0 = *reinterpret_cast<const float4*>(src);
            float4 v1 = *reinterpret_cast<const float4*>(src + 4);
            uint4 o;
            o.x = h2u(__floats2half2_rn(v0.x, v0.y));
            o.y = h2u(__floats2half2_rn(v0.z, v0.w));
            o.z = h2u(__floats2half2_rn(v1.x, v1.y));
            o.w = h2u(__floats2half2_rn(v1.z, v1.w));
            *reinterpret_cast<uint4*>(dynsm + r * BROWF + kg * 2) = o;
        }
    }
    __syncthreads();

    float acc[2][4][4];
    #pragma unroll
    for (int s = 0; s < 2; s++)
        #pragma unroll
        for (int j = 0; j < 4; j++)
            #pragma unroll
            for (int d = 0; d < 4; d++) acc[s][j][d] = 0.f;

    // ---- mainloop: 32 ksteps, no barriers ----
    #pragma unroll 2
    for (int kt = 0; kt < 8; kt++) {
        #pragma unroll
        for (int ks = 0; ks < 4; ks++) {
            const int kstep = kt * 4 + ks;
            long aIdx = (((long)(warp * 32 + kstep)) * 2) * 32 + lane;
            uint4 A0 = g_w1pack[aIdx];        // s=0: n0, n0+8
            uint4 A1 = g_w1pack[aIdx + 32];   // s=1: n0+16, n0+24

            #pragma unroll
            for (int jp = 0; jp < 2; jp++) {
                int jm = jp * 2 + lmJ;
                uint32_t addr = sbAddr + (jm * 8 + lmRow) * BROWF
                              + kstep * 32 + lmPiece * 16;
                uint32_t r0, r1, r2, r3;
                ldsm4(r0, r1, r2, r3, addr);
                mma_f16(acc[0][jp * 2],     A0.x, A0.y, A0.z, A0.w, r0, r1);
                mma_f16(acc[1][jp * 2],     A1.x, A1.y, A1.z, A1.w, r0, r1);
                mma_f16(acc[0][jp * 2 + 1], A0.x, A0.y, A0.z, A0.w, r2, r3);
                mma_f16(acc[1][jp * 2 + 1], A1.x, A1.y, A1.z, A1.w, r2, r3);
            }
        }
    }
    __syncthreads();   // B tile dead; sT aliases it

    // Epilogue pass 1: +b1, relu, fp16 -> sT [m 32][hid 256 (stride 264)]
    #pragma unroll
    for (int s = 0; s < 2; s++) {
        int n_g = warp * 32 + s * 16 + g;
        float bn0 = __ldg(&b1[n_g]);
        float bn8 = __ldg(&b1[n_g + 8]);
        #pragma unroll
        for (int j = 0; j < 4; j++) {
            int m_loc = j * 8 + t * 2;
            sT[m_loc * 264 + n_g]           = __float2half(fmaxf(acc[s][j][0] + bn0, 0.f));
            sT[(m_loc + 1) * 264 + n_g]     = __float2half(fmaxf(acc[s][j][1] + bn0, 0.f));
            sT[m_loc * 264 + n_g + 8]       = __float2half(fmaxf(acc[s][j][2] + bn8, 0.f));
            sT[(m_loc + 1) * 264 + n_g + 8] = __float2half(fmaxf(acc[s][j][3] + bn8, 0.f));
        }
    }
    __syncthreads();

    // Epilogue pass 2: trans = h @ W2 + b2 -> smem tile [32][65]
    {
        const int mb = warp & 1;
        const int nq = warp >> 1;

        float acc2[2][4];
        #pragma unroll
        for (int nbl = 0; nbl < 2; nbl++)
            #pragma unroll
            for (int d = 0; d < 4; d++) acc2[nbl][d] = 0.f;

        #pragma unroll
        for (int kt = 0; kt < 16; kt++) {
            uint32_t addr = sbAddr + (mb * 16 + (lane & 15)) * 528
                          + kt * 32 + (lane >> 4) * 16;
            uint32_t a0, a1, a2, a3;
            ldsm4(a0, a1, a2, a3, addr);
            #pragma unroll
            for (int nbl = 0; nbl < 2; nbl++) {
                int nb = nq * 2 + nbl;
                uint2 bf = __ldg(&g_w2pack[((long)kt * 8 + nb) * 32 + lane]);
                mma_f16(acc2[nbl], a0, a1, a2, a3, bf.x, bf.y);
            }
        }

        #pragma unroll
        for (int nbl = 0; nbl < 2; nbl++) {
            int n = (nq * 2 + nbl) * 8 + t * 2;
            int r0i = mb * 16 + g;
            if (n < S_) {
                float bn0 = __ldg(&b2[n]);
                sTr[r0i * 65 + n]       = acc2[nbl][0] + bn0;
                sTr[(r0i + 8) * 65 + n] = acc2[nbl][2] + bn0;
                if (n + 1 < S_) {
                    float bn1 = __ldg(&b2[n + 1]);
                    sTr[r0i * 65 + n + 1]       = acc2[nbl][1] + bn1;
                    sTr[(r0i + 8) * 65 + n + 1] = acc2[nbl][3] + bn1;
                }
            }
        }
    }
    __syncthreads();

    const long mB = (long)blockIdx.x * 32;

    // boundary trans rows for the cleanup kernel (rows 0 and 31)
    if (tid < S_ && mB < M1)
        g_trans[mB * TRS + tid] = sTr[tid];
    if (tid >= 128 && tid < 128 + S_ && mB + 31 < M1)
        g_trans[(mB + 31) * TRS + (tid - 128)] = sTr[31 * 65 + (tid - 128)];

    // Fused align: warp handles rows warp*4 .. warp*4+3
    const bool has1 = (lane + 32 < S_);
    #pragma unroll
    for (int jj = 0; jj < 4; jj++) {
        const int i = warp * 4 + jj;
        const long mr = mB + i;
        if (mr >= M1) break;
        const int bb = (int)(mr / TM1);
        const int ti = (int)(mr - (long)bb * TM1);
        const float* Lb = logits + (long)bb * T_ * S_;

        float tri0 = sTr[i * 65 + lane];
        float tri1 = has1 ? sTr[i * 65 + lane + 32] : 0.f;

        if (ti == 0) {
            // output (bb, 0): f0 + lp[1] + tr[0]
            float a0 = __ldg(&Lb[lane]);
            float a1 = has1 ? __ldg(&Lb[lane + 32]) : -INFINITY;
            float mx = fmaxf(a0, a1);
            #pragma unroll
            for (int o = 16; o > 0; o >>= 1) mx = fmaxf(mx, __shfl_xor_sync(0xffffffff, mx, o));
            float se = __expf(a0 - mx) + (has1 ? __expf(a1 - mx) : 0.f);
            #pragma unroll
            for (int o = 16; o > 0; o >>= 1) se += __shfl_xor_sync(0xffffffff, se, o);
            float lse = mx + __logf(se);
            int k0 = __ldg(&kw[bb * 32]);
            float logp0 = __ldg(&Lb[k0]) - lse;
            float v0 = ((lane == 0) ? logp0 : 0.f) + __ldg(&Lb[S_ + lane]) + tri0;
            float v1 = has1 ? (__ldg(&Lb[S_ + lane + 32]) + tri1) : -INFINITY;
            softmax_emit(v0, v1, has1, out + (long)bb * T_ * S_, lane);
        } else if (i > 0) {
            // output (bb, ti): lp[ti] + lp[ti+1] + tr[ti-1] + tr[ti]
            float v0 = __ldg(&Lb[(long)ti * S_ + lane]) + __ldg(&Lb[(long)(ti + 1) * S_ + lane])
                     + sTr[(i - 1) * 65 + lane] + tri0;
            float v1 = has1
                ? (__ldg(&Lb[(long)ti * S_ + lane + 32]) + __ldg(&Lb[(long)(ti + 1) * S_ + lane + 32])
                   + sTr[(i - 1) * 65 + lane + 32] + tri1)
                : -INFINITY;
            softmax_emit(v0, v1, has1, out + ((long)bb * T_ + ti) * S_, lane);
        }
        if (ti == TM1 - 1) {
            // output (bb, T-1): lp[T-1] + tr[T-2]
            float v0 = __ldg(&Lb[(long)(T_ - 1) * S_ + lane]) + tri0;
            float v1 = has1 ? (__ldg(&Lb[(long)(T_ - 1) * S_ + lane + 32]) + tri1) : -INFINITY;
            softmax_emit(v0, v1, has1, out + ((long)bb * T_ + T_ - 1) * S_, lane);
        }
    }
}

// ===========================================================================
// Cleanup: tile-boundary outputs (m = 32c, c>=1, ti>=1) from g_trans rows.
// ===========================================================================
__global__ __launch_bounds__(256) void cleanup_kernel(
    const float* __restrict__ logits, float* __restrict__ out)
{
    const int c = blockIdx.x * 8 + (threadIdx.x >> 5) + 1;   // 1..2000
    const long m = (long)c * 32;
    if (m >= M1) return;
    const int b = (int)(m / TM1);
    const int t = (int)(m - (long)b * TM1);   // ti >= 1 always for these m

    const int lane = threadIdx.x & 31;
    const bool has1 = (lane + 32 < S_);
    const float* Lb = logits + (long)b * T_ * S_;

    float v0 = __ldg(&Lb[(long)t * S_ + lane]) + __ldg(&Lb[(long)(t + 1) * S_ + lane])
             + g_trans[(m - 1) * TRS + lane] + g_trans[m * TRS + lane];
    float v1 = has1
        ? (__ldg(&Lb[(long)t * S_ + lane + 32]) + __ldg(&Lb[(long)(t + 1) * S_ + lane + 32])
           + g_trans[(m - 1) * TRS + lane + 32] + g_trans[m * TRS + lane + 32])
        : -INFINITY;
    softmax_emit(v0, v1, has1, out + ((long)b * T_ + t) * S_, lane);
}

// ===========================================================================
extern "C" void kernel_launch(void* const* d_in, const int* in_sizes, int n_in,
                              void* d_out, int out_size) {
    const float* logits = (const float*)d_in[0];   // (B,T,S)
    const float* emb    = (const float*)d_in[1];   // (B,T,H)
    const int*   kw     = (const int*)  d_in[2];   // (B,32)
    const float* W1     = (const float*)d_in[3];   // (2H,H)
    const float* b1     = (const float*)d_in[4];   // (H,)
    const float* W2     = (const float*)d_in[5];   // (H,S)
    const float* b2     = (const float*)d_in[6];   // (S,)
    float*       out    = (float*)d_out;           // (B,T,S)

    const int smem1 = 32 * BROWF;          // 33280 (holds sT alias + trans tile)
    cudaFuncSetAttribute(gemm_fused, cudaFuncAttributeMaxDynamicSharedMemorySize, smem1);

    prep_weights<<<272, 256>>>(W1, W2);
    gemm_fused<<<2000, 256, smem1>>>(emb, b1, b2, logits, kw, out);
    cleanup_kernel<<<250, 256>>>(logits, out);
}

// round 15
// speedup vs baseline: 1.1821x; 1.1821x over previous
#include <cuda_runtime.h>
#include <cuda_fp16.h>
#include <math.h>
#include <cstdint>

#define B_   32
#define T_   2000
#define H_   256
#define S_   63
#define TRS  64              // g_trans row stride (padded)
#define TM1  1999            // T-1
#define M1   63968           // B*(T-1)
#define M1P  64000           // padded row count
#define K1   512             // 2*H
#define N1   256             // H

// Scratch (device globals: allocation-guard safe)
__device__ __align__(16) float    g_trans[M1P * TRS];     // transition scores (stride 64)
__device__ __align__(16) uint4    g_w1pack[16384];        // W1^T fp16 A-frags
__device__ __align__(16) uint2    g_w2pack[4096];         // W2 fp16 B-frags

__device__ __forceinline__ uint32_t h2u(__half2 h) {
    return *reinterpret_cast<uint32_t*>(&h);
}

__device__ __forceinline__ void mma_f16(float* c, uint32_t a0, uint32_t a1,
                                        uint32_t a2, uint32_t a3,
                                        uint32_t b0, uint32_t b1) {
    asm volatile(
        "mma.sync.aligned.m16n8k16.row.col.f32.f16.f16.f32 "
        "{%0,%1,%2,%3}, {%4,%5,%6,%7}, {%8,%9}, {%0,%1,%2,%3};"
        : "+f"(c[0]), "+f"(c[1]), "+f"(c[2]), "+f"(c[3])
        : "r"(a0), "r"(a1), "r"(a2), "r"(a3), "r"(b0), "r"(b1));
}

__device__ __forceinline__ void ldsm4(uint32_t& r0, uint32_t& r1,
                                      uint32_t& r2, uint32_t& r3, uint32_t addr) {
    asm volatile("ldmatrix.sync.aligned.m8n8.x4.shared.b16 {%0,%1,%2,%3}, [%4];"
                 : "=r"(r0), "=r"(r1), "=r"(r2), "=r"(r3) : "r"(addr));
}

__device__ __forceinline__ uint32_t smem_u32(const void* p) {
    uint32_t a;
    asm("{ .reg .u64 t; cvta.to.shared.u64 t, %1; cvt.u32.u64 %0, t; }"
        : "=r"(a) : "l"(p));
    return a;
}

// ===========================================================================
// Prep: coalesced W1 pack (blocks 0..255) + W2 pack (blocks 256..271).
// ===========================================================================
__global__ __launch_bounds__(256) void prep_weights(
    const float* __restrict__ W1, const float* __restrict__ W2)
{
    if (blockIdx.x < 256) {
        int idx = blockIdx.x * 256 + threadIdx.x;   // 0..65535
        int n  = idx & 255;
        int kp = idx >> 8;                          // 0..255, k0 = 2*kp
        __half2 v = __floats2half2_rn(W1[(long)(kp * 2) * N1 + n],
                                      W1[(long)(kp * 2 + 1) * N1 + n]);
        int kstep = kp >> 3;
        int rem   = kp & 7;
        int sub   = rem >> 2;
        int tq    = rem & 3;
        int q   = n >> 5;
        int nr  = n & 31;
        int s   = nr >> 4;
        int w16 = nr & 15;
        int g8  = w16 >> 3;
        int gg  = w16 & 7;
        int lane = gg * 4 + tq;
        long fid = ((long)(q * 32 + kstep) * 2 + s) * 32 + lane;
        reinterpret_cast<uint32_t*>(g_w1pack)[fid * 4 + sub * 2 + g8] = h2u(v);
    } else {
        int idx  = (blockIdx.x - 256) * 256 + threadIdx.x;
        if (idx >= 4096) return;
        int lane = idx & 31;
        int nb   = (idx >> 5) & 7;
        int kt   = idx >> 8;
        int k = kt * 16 + (lane & 3) * 2;
        int n = nb * 8 + (lane >> 2);
        float w00 = (n < S_) ? W2[(long)k * S_ + n]       : 0.f;
        float w01 = (n < S_) ? W2[(long)(k + 1) * S_ + n] : 0.f;
        float w10 = (n < S_) ? W2[(long)(k + 8) * S_ + n] : 0.f;
        float w11 = (n < S_) ? W2[(long)(k + 9) * S_ + n] : 0.f;
        uint2 o;
        o.x = h2u(__floats2half2_rn(w00, w01));
        o.y = h2u(__floats2half2_rn(w10, w11));
        g_w2pack[idx] = o;
    }
}

// ===========================================================================
// Fused GEMM1+GEMM2, M=32 tiles (grid 2000), FULL-K staging, occupancy 3:
//   stage: pairs tile [32 rows][512 k] fp16, row stride 1040B (conflict-free).
//   mainloop: 32 ksteps, pure LDG(A-frag)+ldsm+MMA, zero barriers.
//   epilogue: +b1/relu -> sT (aliased), then trans = h @ W2 + b2 -> g_trans.
// ===========================================================================
#define BROWF 1040   // full-K B row stride bytes (1024 data + 16 pad; ≡16 mod 128)
__global__ __launch_bounds__(256, 3) void gemm1_fused(
    const float* __restrict__ emb, const float* __restrict__ b1,
    const float* __restrict__ b2)
{
    extern __shared__ __align__(16) char dynsm[];
    __half* sT = reinterpret_cast<__half*>(dynsm);   // [32][264] epilogue h tile (alias)
    const uint32_t sbAddr = smem_u32(dynsm);

    const int tid  = threadIdx.x;
    const int warp = tid >> 5;     // hidden 32-block (0..7)
    const int lane = tid & 31;
    const int g    = lane >> 2;
    const int t    = lane & 3;

    const int lmJ     = (lane >> 4);
    const int lmPiece = (lane >> 3) & 1;
    const int lmRow   = lane & 7;

    // staging mapping: row r = tid>>3; 8 chunks of 8 k at kg = (tid&7)*8 + u*64
    const int r  = tid >> 3;             // 0..31
    const int c8 = (tid & 7) * 8;        // 0..56
    const int mBase = blockIdx.x * 32;
    int m = mBase + r;
    if (m >= M1) m = M1 - 1;
    const int b = m / TM1;
    const int tt = m - b * TM1;
    const float* rowT  = emb + ((long)b * T_ + tt) * H_;   // pairs k>=256
    const float* rowT1 = rowT + H_;                        // pairs k<256

    // ---- stage full K=512 (one pass, conflict-free stores) ----
    {
        #pragma unroll
        for (int u = 0; u < 8; u++) {
            const int kg = c8 + u * 64;
            const float* src = (kg < H_) ? (rowT1 + kg) : (rowT + (kg - H_));
            float4 v0 = *reinterpret_cast<const float4*>(src);
            float4 v1 = *reinterpret_cast<const float4*>(src + 4);
            uint4 o;
            o.x = h2u(__floats2half2_rn(v0.x, v0.y));
            o.y = h2u(__floats2half2_rn(v0.z, v0.w));
            o.z = h2u(__floats2half2_rn(v1.x, v1.y));
            o.w = h2u(__floats2half2_rn(v1.z, v1.w));
            *reinterpret_cast<uint4*>(dynsm + r * BROWF + kg * 2) = o;
        }
    }
    __syncthreads();

    float acc[2][4][4];
    #pragma unroll
    for (int s = 0; s < 2; s++)
        #pragma unroll
        for (int j = 0; j < 4; j++)
            #pragma unroll
            for (int d = 0; d < 4; d++) acc[s][j][d] = 0.f;

    // ---- mainloop: 32 ksteps, no barriers ----
    #pragma unroll 2
    for (int kt = 0; kt < 8; kt++) {
        #pragma unroll
        for (int ks = 0; ks < 4; ks++) {
            const int kstep = kt * 4 + ks;
            long aIdx = (((long)(warp * 32 + kstep)) * 2) * 32 + lane;
            uint4 A0 = g_w1pack[aIdx];        // s=0: n0, n0+8
            uint4 A1 = g_w1pack[aIdx + 32];   // s=1: n0+16, n0+24

            #pragma unroll
            for (int jp = 0; jp < 2; jp++) {
                int jm = jp * 2 + lmJ;
                uint32_t addr = sbAddr + (jm * 8 + lmRow) * BROWF
                              + kstep * 32 + lmPiece * 16;
                uint32_t r0, r1, r2, r3;
                ldsm4(r0, r1, r2, r3, addr);
                mma_f16(acc[0][jp * 2],     A0.x, A0.y, A0.z, A0.w, r0, r1);
                mma_f16(acc[1][jp * 2],     A1.x, A1.y, A1.z, A1.w, r0, r1);
                mma_f16(acc[0][jp * 2 + 1], A0.x, A0.y, A0.z, A0.w, r2, r3);
                mma_f16(acc[1][jp * 2 + 1], A1.x, A1.y, A1.z, A1.w, r2, r3);
            }
        }
    }
    __syncthreads();   // B tile dead; sT aliases it

    // Epilogue pass 1: +b1, relu, fp16 -> sT [m 32][hid 256 (stride 264)]
    #pragma unroll
    for (int s = 0; s < 2; s++) {
        int n_g = warp * 32 + s * 16 + g;
        float bn0 = __ldg(&b1[n_g]);
        float bn8 = __ldg(&b1[n_g + 8]);
        #pragma unroll
        for (int j = 0; j < 4; j++) {
            int m_loc = j * 8 + t * 2;
            sT[m_loc * 264 + n_g]           = __float2half(fmaxf(acc[s][j][0] + bn0, 0.f));
            sT[(m_loc + 1) * 264 + n_g]     = __float2half(fmaxf(acc[s][j][1] + bn0, 0.f));
            sT[m_loc * 264 + n_g + 8]       = __float2half(fmaxf(acc[s][j][2] + bn8, 0.f));
            sT[(m_loc + 1) * 264 + n_g + 8] = __float2half(fmaxf(acc[s][j][3] + bn8, 0.f));
        }
    }
    __syncthreads();

    // Epilogue pass 2 (fused gemm2): trans = h @ W2 + b2
    //   warp w: mb = w&1 (m16-block), nq = w>>1 (16 of 64 n-cols).
    {
        const int mb = warp & 1;
        const int nq = warp >> 1;

        float acc2[2][4];
        #pragma unroll
        for (int nbl = 0; nbl < 2; nbl++)
            #pragma unroll
            for (int d = 0; d < 4; d++) acc2[nbl][d] = 0.f;

        #pragma unroll
        for (int kt = 0; kt < 16; kt++) {
            uint32_t addr = sbAddr + (mb * 16 + (lane & 15)) * 528
                          + kt * 32 + (lane >> 4) * 16;
            uint32_t a0, a1, a2, a3;
            ldsm4(a0, a1, a2, a3, addr);
            #pragma unroll
            for (int nbl = 0; nbl < 2; nbl++) {
                int nb = nq * 2 + nbl;
                uint2 bf = __ldg(&g_w2pack[((long)kt * 8 + nb) * 32 + lane]);
                mma_f16(acc2[nbl], a0, a1, a2, a3, bf.x, bf.y);
            }
        }

        const long mB = (long)blockIdx.x * 32;
        #pragma unroll
        for (int nbl = 0; nbl < 2; nbl++) {
            int n = (nq * 2 + nbl) * 8 + t * 2;
            long r0 = mB + mb * 16 + g;
            long r1 = r0 + 8;
            if (n + 1 < S_) {
                float bn0 = __ldg(&b2[n]);
                float bn1 = __ldg(&b2[n + 1]);
                float2 v0 = make_float2(acc2[nbl][0] + bn0, acc2[nbl][1] + bn1);
                float2 v1 = make_float2(acc2[nbl][2] + bn0, acc2[nbl][3] + bn1);
                *reinterpret_cast<float2*>(&g_trans[r0 * TRS + n]) = v0;
                *reinterpret_cast<float2*>(&g_trans[r1 * TRS + n]) = v1;
            } else if (n < S_) {
                float bn0 = __ldg(&b2[n]);
                g_trans[r0 * TRS + n] = acc2[nbl][0] + bn0;
                g_trans[r1 * TRS + n] = acc2[nbl][2] + bn0;
            }
        }
    }
}

// ===========================================================================
// Align: one warp per 8 consecutive t of one b, register-carried rows.
// ===========================================================================
#define TW 8
__global__ __launch_bounds__(256) void align_kernel(
    const float* __restrict__ logits, const int* __restrict__ kw,
    float* __restrict__ out)
{
    const int warp = threadIdx.x >> 5;
    const int lane = threadIdx.x & 31;
    const int task = blockIdx.x * 8 + warp;       // 0..7999
    const int b = task / (T_ / TW);
    const int t0 = (task - b * (T_ / TW)) * TW;

    const float* Lb  = logits  + (long)b * T_ * S_;
    const float* Trb = g_trans + (long)b * TM1 * TRS;

    const int s0 = lane;
    const int s1 = lane + 32;
    const bool has1 = (s1 < S_);

    float lpc0 = __ldg(&Lb[(long)t0 * S_ + s0]);
    float lpc1 = has1 ? __ldg(&Lb[(long)t0 * S_ + s1]) : 0.f;
    float trp0 = 0.f, trp1 = 0.f;
    if (t0 > 0) {
        trp0 = __ldg(&Trb[(long)(t0 - 1) * TRS + s0]);
        if (has1) trp1 = __ldg(&Trb[(long)(t0 - 1) * TRS + s1]);
    }

    #pragma unroll
    for (int i = 0; i < TW; i++) {
        const int t = t0 + i;
        float lpn0 = 0.f, lpn1 = 0.f, trc0 = 0.f, trc1 = 0.f;
        if (t < T_ - 1) {
            lpn0 = __ldg(&Lb[(long)(t + 1) * S_ + s0]);
            trc0 = __ldg(&Trb[(long)t * TRS + s0]);
            if (has1) {
                lpn1 = __ldg(&Lb[(long)(t + 1) * S_ + s1]);
                trc1 = __ldg(&Trb[(long)t * TRS + s1]);
            }
        }

        float v0, v1;
        if (t == 0) {
            float a0 = lpc0;
            float a1 = has1 ? lpc1 : -INFINITY;
            float mx = fmaxf(a0, a1);
            #pragma unroll
            for (int o = 16; o > 0; o >>= 1) mx = fmaxf(mx, __shfl_xor_sync(0xffffffff, mx, o));
            float se = __expf(a0 - mx) + (has1 ? __expf(a1 - mx) : 0.f);
            #pragma unroll
            for (int o = 16; o > 0; o >>= 1) se += __shfl_xor_sync(0xffffffff, se, o);
            float lse = mx + __logf(se);
            int k0 = __ldg(&kw[b * 32]);
            float logp0 = __ldg(&Lb[k0]) - lse;
            v0 = ((s0 == 0) ? logp0 : 0.f) + lpn0 + trc0;
            v1 = has1 ? (lpn1 + trc1) : -INFINITY;
        } else if (t == T_ - 1) {
            v0 = lpc0 + trp0;
            v1 = has1 ? (lpc1 + trp1) : -INFINITY;
        } else {
            v0 = lpc0 + lpn0 + trp0 + trc0;
            v1 = has1 ? (lpc1 + lpn1 + trp1 + trc1) : -INFINITY;
        }

        float mx = fmaxf(v0, v1);
        #pragma unroll
        for (int o = 16; o > 0; o >>= 1) mx = fmaxf(mx, __shfl_xor_sync(0xffffffff, mx, o));
        float e0 = __expf(v0 - mx);
        float e1 = has1 ? __expf(v1 - mx) : 0.f;
        float sum = e0 + e1;
        #pragma unroll
        for (int o = 16; o > 0; o >>= 1) sum += __shfl_xor_sync(0xffffffff, sum, o);
        float inv = 1.f / sum;

        float* ob = out + ((long)b * T_ + t) * S_;
        ob[s0] = e0 * inv;
        if (has1) ob[s1] = e1 * inv;

        lpc0 = lpn0; lpc1 = lpn1;
        trp0 = trc0; trp1 = trc1;
    }
}

// ===========================================================================
extern "C" void kernel_launch(void* const* d_in, const int* in_sizes, int n_in,
                              void* d_out, int out_size) {
    const float* logits = (const float*)d_in[0];   // (B,T,S)
    const float* emb    = (const float*)d_in[1];   // (B,T,H)
    const int*   kw     = (const int*)  d_in[2];   // (B,32)
    const float* W1     = (const float*)d_in[3];   // (2H,H)
    const float* b1     = (const float*)d_in[4];   // (H,)
    const float* W2     = (const float*)d_in[5];   // (H,S)
    const float* b2     = (const float*)d_in[6];   // (S,)
    float*       out    = (float*)d_out;           // (B,T,S)

    const int smem1 = 32 * BROWF;          // 33280; x3 CTAs = 99.8KB < 228KB
    cudaFuncSetAttribute(gemm1_fused, cudaFuncAttributeMaxDynamicSharedMemorySize, smem1);

    prep_weights<<<272, 256>>>(W1, W2);
    gemm1_fused<<<2000, 256, smem1>>>(emb, b1, b2);
    align_kernel<<<(B_ * (T_ / TW)) / 8, 256>>>(logits, kw, out);
}